// round 12
// baseline (speedup 1.0000x reference)
#include <cuda_runtime.h>
#include <math.h>
#include <stdint.h>

// Problem constants
#define BB   2
#define TT   1024
#define LL   6
#define HH   16
#define EE   1024
#define FF_  4096
#define HD_  64
#define VV   50257
#define EPSF 1e-5f

// ---------------- scratch (device globals; no allocations allowed) ----------
__device__ float g_x  [BB*TT*EE];     // residual stream
__device__ float g_h  [BB*TT*EE];     // layernorm output
__device__ float g_qkv[BB*TT*3*EE];   // qkv projections
__device__ float g_y  [BB*TT*EE];     // attention output
__device__ float g_ff [BB*TT*FF_];    // MLP hidden

// ---------------- embedding: x = wte[idx] + wpe[t] ---------------------------
__global__ void k_embed(const int* __restrict__ idx,
                        const float* __restrict__ wte,
                        const float* __restrict__ wpe) {
    int row = blockIdx.x;          // b*TT + t
    int t   = row % TT;
    int tok = idx[row];
    const float* wt = wte + (size_t)tok * EE;
    const float* wp = wpe + (size_t)t   * EE;
    float* xr = g_x + (size_t)row * EE;
    for (int e = threadIdx.x; e < EE; e += blockDim.x)
        xr[e] = wt[e] + wp[e];
}

// ---------------- layernorm (one block of 256 per row, warp-shuffle reduce) --
__global__ void __launch_bounds__(256)
k_ln(const float* __restrict__ x,
     const float* __restrict__ g,
     const float* __restrict__ b,
     float* __restrict__ out) {
    int row = blockIdx.x;
    const float* xr = x + (size_t)row * EE;
    int tid = threadIdx.x;

    float4 v = ((const float4*)xr)[tid];
    float s  = v.x + v.y + v.z + v.w;
    float s2 = v.x*v.x + v.y*v.y + v.z*v.z + v.w*v.w;

    #pragma unroll
    for (int o = 16; o > 0; o >>= 1) {
        s  += __shfl_xor_sync(0xffffffffu, s,  o);
        s2 += __shfl_xor_sync(0xffffffffu, s2, o);
    }
    __shared__ float ws[8], wq[8];
    int warp = tid >> 5, lane = tid & 31;
    if (lane == 0) { ws[warp] = s; wq[warp] = s2; }
    __syncthreads();
    if (warp == 0) {
        float a = (lane < 8) ? ws[lane] : 0.f;
        float c = (lane < 8) ? wq[lane] : 0.f;
        #pragma unroll
        for (int o = 4; o > 0; o >>= 1) {
            a += __shfl_xor_sync(0xffffffffu, a, o);
            c += __shfl_xor_sync(0xffffffffu, c, o);
        }
        if (lane == 0) { ws[0] = a; wq[0] = c; }
    }
    __syncthreads();
    float m   = ws[0] * (1.0f / EE);
    float var = wq[0] * (1.0f / EE) - m * m;
    float inv = rsqrtf(var + EPSF);

    float4 gv = ((const float4*)g)[tid];
    float4 bv = ((const float4*)b)[tid];
    float4 o4;
    o4.x = (v.x - m) * inv * gv.x + bv.x;
    o4.y = (v.y - m) * inv * gv.y + bv.y;
    o4.z = (v.z - m) * inv * gv.z + bv.z;
    o4.w = (v.w - m) * inv * gv.w + bv.w;
    ((float4*)(out + (size_t)row * EE))[tid] = o4;
}

__device__ __forceinline__ float gelu_exact(float v) {
    return 0.5f * v * (1.0f + erff(v * 0.70710678118654752f));
}

// ---------------- GEMM NN: C = act(A[M,K] @ B[K,N] + bias (+resid)) ----------
// 128x128 tile, K-tile 16, 256 threads, 8x8 microtile.
// Double-buffered smem, global->reg prefetch, 1 sync per K-tile.
// Requires: M,N multiples of 128, K multiple of 16 (true for all layer GEMMs;
// row strides multiple of 4 floats so float4 accesses stay 16B-aligned).
template<bool GELU, bool RESID>
__global__ void __launch_bounds__(256)
k_gemm_nn(const float* __restrict__ A, const float* __restrict__ Bw,
          const float* __restrict__ bias, float* __restrict__ C,
          int M, int N, int K) {
    __shared__ float As[2][16][128];
    __shared__ float Bs[2][16][128];
    int tid = threadIdx.x;
    int tx = tid & 15, ty = tid >> 4;       // 16x16 thread grid
    int rb = blockIdx.y * 128, cb = blockIdx.x * 128;

    int arow = tid >> 1;                    // 0..127
    int ak   = (tid & 1) * 8;               // 0 or 8
    int bkr  = tid >> 5;                    // 0..7
    int bc   = (tid & 31) * 4;              // 0..124

    const float* Aptr = A  + (size_t)(rb + arow) * K;
    const float* Bp0  = Bw + (size_t)bkr * N + cb + bc;

    float4 a0 = *(const float4*)(Aptr + ak);
    float4 a1 = *(const float4*)(Aptr + ak + 4);
    float4 b0 = *(const float4*)(Bp0);
    float4 b1 = *(const float4*)(Bp0 + (size_t)8 * N);

    As[0][ak+0][arow] = a0.x; As[0][ak+1][arow] = a0.y;
    As[0][ak+2][arow] = a0.z; As[0][ak+3][arow] = a0.w;
    As[0][ak+4][arow] = a1.x; As[0][ak+5][arow] = a1.y;
    As[0][ak+6][arow] = a1.z; As[0][ak+7][arow] = a1.w;
    *(float4*)&Bs[0][bkr    ][bc] = b0;
    *(float4*)&Bs[0][bkr + 8][bc] = b1;
    __syncthreads();

    float acc[8][8];
    #pragma unroll
    for (int i = 0; i < 8; i++)
        #pragma unroll
        for (int j = 0; j < 8; j++) acc[i][j] = 0.f;

    int nk = K >> 4;
    int p = 0;
    for (int kt = 0; kt < nk; kt++) {
        if (kt + 1 < nk) {
            int k0 = (kt + 1) << 4;
            a0 = *(const float4*)(Aptr + k0 + ak);
            a1 = *(const float4*)(Aptr + k0 + ak + 4);
            b0 = *(const float4*)(Bp0 + (size_t)k0 * N);
            b1 = *(const float4*)(Bp0 + (size_t)(k0 + 8) * N);
        }
        #pragma unroll
        for (int kk = 0; kk < 16; kk++) {
            float4 av0 = *(const float4*)&As[p][kk][ty * 8];
            float4 av1 = *(const float4*)&As[p][kk][ty * 8 + 4];
            float4 bv0 = *(const float4*)&Bs[p][kk][tx * 4];
            float4 bv1 = *(const float4*)&Bs[p][kk][64 + tx * 4];
            float a[8] = {av0.x, av0.y, av0.z, av0.w, av1.x, av1.y, av1.z, av1.w};
            float bbv[8] = {bv0.x, bv0.y, bv0.z, bv0.w, bv1.x, bv1.y, bv1.z, bv1.w};
            #pragma unroll
            for (int i = 0; i < 8; i++)
                #pragma unroll
                for (int j = 0; j < 8; j++)
                    acc[i][j] = fmaf(a[i], bbv[j], acc[i][j]);
        }
        if (kt + 1 < nk) {
            int q = p ^ 1;
            As[q][ak+0][arow] = a0.x; As[q][ak+1][arow] = a0.y;
            As[q][ak+2][arow] = a0.z; As[q][ak+3][arow] = a0.w;
            As[q][ak+4][arow] = a1.x; As[q][ak+5][arow] = a1.y;
            As[q][ak+6][arow] = a1.z; As[q][ak+7][arow] = a1.w;
            *(float4*)&Bs[q][bkr    ][bc] = b0;
            *(float4*)&Bs[q][bkr + 8][bc] = b1;
        }
        __syncthreads();
        p ^= 1;
    }

    float4 bias0 = *(const float4*)(bias + cb + tx * 4);
    float4 bias1 = *(const float4*)(bias + cb + 64 + tx * 4);

    #pragma unroll
    for (int i = 0; i < 8; i++) {
        int r = rb + ty * 8 + i;
        float* crow = C + (size_t)r * N + cb;
        float4 v0, v1;
        v0.x = acc[i][0] + bias0.x; v0.y = acc[i][1] + bias0.y;
        v0.z = acc[i][2] + bias0.z; v0.w = acc[i][3] + bias0.w;
        v1.x = acc[i][4] + bias1.x; v1.y = acc[i][5] + bias1.y;
        v1.z = acc[i][6] + bias1.z; v1.w = acc[i][7] + bias1.w;
        if (RESID) {
            float4 r0 = *(const float4*)(crow + tx * 4);
            float4 r1 = *(const float4*)(crow + 64 + tx * 4);
            v0.x += r0.x; v0.y += r0.y; v0.z += r0.z; v0.w += r0.w;
            v1.x += r1.x; v1.y += r1.y; v1.z += r1.z; v1.w += r1.w;
        }
        if (GELU) {
            v0.x = gelu_exact(v0.x); v0.y = gelu_exact(v0.y);
            v0.z = gelu_exact(v0.z); v0.w = gelu_exact(v0.w);
            v1.x = gelu_exact(v1.x); v1.y = gelu_exact(v1.y);
            v1.z = gelu_exact(v1.z); v1.w = gelu_exact(v1.w);
        }
        *(float4*)(crow + tx * 4)      = v0;
        *(float4*)(crow + 64 + tx * 4) = v1;
    }
}

// ---------------- GEMM NT (head): C[M,N] = A[M,K] @ B[N,K]^T ----------------
// B rows are n-rows (K-contiguous), N edge-guarded (V=50257).
// NOTE: N is ODD, so C row stride is not 16B-aligned -> epilogue must use
// SCALAR stores (float4 store here caused the R10 'misaligned address' fault).
__global__ void __launch_bounds__(256)
k_gemm_nt(const float* __restrict__ A, const float* __restrict__ Bw,
          float* __restrict__ C, int M, int N, int K) {
    __shared__ float As[2][16][128];
    __shared__ float Bs[2][16][128];
    int tid = threadIdx.x;
    int tx = tid & 15, ty = tid >> 4;
    int rb = blockIdx.y * 128, cb = blockIdx.x * 128;

    int row = tid >> 1;            // 0..127 (A m-row / B n-row)
    int kq  = (tid & 1) * 8;       // 0 or 8

    const float* Aptr = A + (size_t)(rb + row) * K;
    int nidx = cb + row;
    bool nvalid = nidx < N;
    const float* Bptr = Bw + (size_t)(nvalid ? nidx : 0) * K;

    float4 a0 = *(const float4*)(Aptr + kq);
    float4 a1 = *(const float4*)(Aptr + kq + 4);
    float4 b0 = make_float4(0.f,0.f,0.f,0.f), b1 = b0;
    if (nvalid) { b0 = *(const float4*)(Bptr + kq); b1 = *(const float4*)(Bptr + kq + 4); }

    As[0][kq+0][row]=a0.x; As[0][kq+1][row]=a0.y; As[0][kq+2][row]=a0.z; As[0][kq+3][row]=a0.w;
    As[0][kq+4][row]=a1.x; As[0][kq+5][row]=a1.y; As[0][kq+6][row]=a1.z; As[0][kq+7][row]=a1.w;
    Bs[0][kq+0][row]=b0.x; Bs[0][kq+1][row]=b0.y; Bs[0][kq+2][row]=b0.z; Bs[0][kq+3][row]=b0.w;
    Bs[0][kq+4][row]=b1.x; Bs[0][kq+5][row]=b1.y; Bs[0][kq+6][row]=b1.z; Bs[0][kq+7][row]=b1.w;
    __syncthreads();

    float acc[8][8];
    #pragma unroll
    for (int i = 0; i < 8; i++)
        #pragma unroll
        for (int j = 0; j < 8; j++) acc[i][j] = 0.f;

    int nk = K >> 4;
    int p = 0;
    for (int kt = 0; kt < nk; kt++) {
        if (kt + 1 < nk) {
            int k0 = (kt + 1) << 4;
            a0 = *(const float4*)(Aptr + k0 + kq);
            a1 = *(const float4*)(Aptr + k0 + kq + 4);
            if (nvalid) {
                b0 = *(const float4*)(Bptr + k0 + kq);
                b1 = *(const float4*)(Bptr + k0 + kq + 4);
            }
        }
        #pragma unroll
        for (int kk = 0; kk < 16; kk++) {
            float4 av0 = *(const float4*)&As[p][kk][ty * 8];
            float4 av1 = *(const float4*)&As[p][kk][ty * 8 + 4];
            float4 bv0 = *(const float4*)&Bs[p][kk][tx * 4];
            float4 bv1 = *(const float4*)&Bs[p][kk][64 + tx * 4];
            float a[8] = {av0.x, av0.y, av0.z, av0.w, av1.x, av1.y, av1.z, av1.w};
            float bbv[8] = {bv0.x, bv0.y, bv0.z, bv0.w, bv1.x, bv1.y, bv1.z, bv1.w};
            #pragma unroll
            for (int i = 0; i < 8; i++)
                #pragma unroll
                for (int j = 0; j < 8; j++)
                    acc[i][j] = fmaf(a[i], bbv[j], acc[i][j]);
        }
        if (kt + 1 < nk) {
            int q = p ^ 1;
            As[q][kq+0][row]=a0.x; As[q][kq+1][row]=a0.y; As[q][kq+2][row]=a0.z; As[q][kq+3][row]=a0.w;
            As[q][kq+4][row]=a1.x; As[q][kq+5][row]=a1.y; As[q][kq+6][row]=a1.z; As[q][kq+7][row]=a1.w;
            Bs[q][kq+0][row]=b0.x; Bs[q][kq+1][row]=b0.y; Bs[q][kq+2][row]=b0.z; Bs[q][kq+3][row]=b0.w;
            Bs[q][kq+4][row]=b1.x; Bs[q][kq+5][row]=b1.y; Bs[q][kq+6][row]=b1.z; Bs[q][kq+7][row]=b1.w;
        }
        __syncthreads();
        p ^= 1;
    }

    // Scalar epilogue: C rows are misaligned for float4 when N is odd.
    // Lanes still cover contiguous columns, so stores coalesce per sector.
    #pragma unroll
    for (int i = 0; i < 8; i++) {
        int r = rb + ty * 8 + i;
        float* crow = C + (size_t)r * N;
        #pragma unroll
        for (int j = 0; j < 4; j++) {
            int c = cb + tx * 4 + j;
            if (c < N) crow[c] = acc[i][j];
        }
        #pragma unroll
        for (int j = 0; j < 4; j++) {
            int c = cb + 64 + tx * 4 + j;
            if (c < N) crow[c] = acc[i][4 + j];
        }
    }
}

// ---------------- attention: one block per (b, h, q-row), flash-lite --------
__global__ void __launch_bounds__(128)
k_attn(const float* __restrict__ qkv, float* __restrict__ y) {
    int qi = blockIdx.x, h = blockIdx.y, b = blockIdx.z;
    __shared__ float qs[HD_];
    __shared__ float s[TT];
    __shared__ float red[128];
    int tid = threadIdx.x;
    const float scale = 0.125f;   // 1/sqrt(64)

    if (tid < HD_)
        qs[tid] = qkv[((size_t)(b * TT + qi)) * (3 * EE) + h * HD_ + tid] * scale;
    __syncthreads();

    float lmax = -1e30f;
    for (int j = tid; j <= qi; j += 128) {
        const float4* kr = (const float4*)(qkv + ((size_t)(b * TT + j)) * (3 * EE)
                                           + EE + h * HD_);
        float d = 0.f;
        #pragma unroll
        for (int e = 0; e < HD_ / 4; e++) {
            float4 kv = kr[e];
            d += qs[4*e+0]*kv.x + qs[4*e+1]*kv.y + qs[4*e+2]*kv.z + qs[4*e+3]*kv.w;
        }
        s[j] = d;
        lmax = fmaxf(lmax, d);
    }
    red[tid] = lmax;
    __syncthreads();
    for (int o = 64; o > 0; o >>= 1) {
        if (tid < o) red[tid] = fmaxf(red[tid], red[tid + o]);
        __syncthreads();
    }
    float mx = red[0];
    __syncthreads();

    float lsum = 0.f;
    for (int j = tid; j <= qi; j += 128) {
        float p = expf(s[j] - mx);
        s[j] = p;
        lsum += p;
    }
    red[tid] = lsum;
    __syncthreads();
    for (int o = 64; o > 0; o >>= 1) {
        if (tid < o) red[tid] += red[tid + o];
        __syncthreads();
    }
    float inv = 1.0f / red[0];
    __syncthreads();

    int d    = tid & 63;
    int half = tid >> 6;
    float acc = 0.f;
    for (int j = half; j <= qi; j += 2) {
        const float* vr = qkv + ((size_t)(b * TT + j)) * (3 * EE) + 2 * EE + h * HD_;
        acc += s[j] * vr[d];
    }
    red[tid] = acc;
    __syncthreads();
    if (half == 0) {
        float r = (red[tid] + red[tid + 64]) * inv;
        y[((size_t)(b * TT + qi)) * EE + h * HD_ + d] = r;
    }
}

// ---------------- driver ------------------------------------------------------
extern "C" void kernel_launch(void* const* d_in, const int* in_sizes, int n_in,
                              void* d_out, int out_size) {
    const int*   idx   = (const int*)  d_in[0];
    const float* wte   = (const float*)d_in[1];
    const float* wpe   = (const float*)d_in[2];
    const float* ln1_g = (const float*)d_in[3];
    const float* ln1_b = (const float*)d_in[4];
    const float* wqkv  = (const float*)d_in[5];
    const float* bqkv  = (const float*)d_in[6];
    const float* wproj = (const float*)d_in[7];
    const float* bproj = (const float*)d_in[8];
    const float* ln2_g = (const float*)d_in[9];
    const float* ln2_b = (const float*)d_in[10];
    const float* wfc   = (const float*)d_in[11];
    const float* bfc   = (const float*)d_in[12];
    const float* wout  = (const float*)d_in[13];
    const float* bout  = (const float*)d_in[14];
    const float* lnf_g = (const float*)d_in[15];
    const float* lnf_b = (const float*)d_in[16];
    float* logits = (float*)d_out;

    float *gx, *gh, *gqkv, *gy, *gff;
    cudaGetSymbolAddress((void**)&gx,   g_x);
    cudaGetSymbolAddress((void**)&gh,   g_h);
    cudaGetSymbolAddress((void**)&gqkv, g_qkv);
    cudaGetSymbolAddress((void**)&gy,   g_y);
    cudaGetSymbolAddress((void**)&gff,  g_ff);

    const int M = BB * TT;  // 2048

    k_embed<<<M, 256>>>(idx, wte, wpe);

    for (int l = 0; l < LL; l++) {
        // ln1
        k_ln<<<M, 256>>>(gx, ln1_g + (size_t)l * EE, ln1_b + (size_t)l * EE, gh);
        // qkv = h @ wqkv + bqkv   [2048, 3072]
        k_gemm_nn<false, false><<<dim3(3 * EE / 128, M / 128), 256>>>(
            gh, wqkv + (size_t)l * EE * 3 * EE, bqkv + (size_t)l * 3 * EE,
            gqkv, M, 3 * EE, EE);
        // attention
        k_attn<<<dim3(TT, HH, BB), 128>>>(gqkv, gy);
        // x += y @ wproj + bproj
        k_gemm_nn<false, true><<<dim3(EE / 128, M / 128), 256>>>(
            gy, wproj + (size_t)l * EE * EE, bproj + (size_t)l * EE,
            gx, M, EE, EE);
        // ln2
        k_ln<<<M, 256>>>(gx, ln2_g + (size_t)l * EE, ln2_b + (size_t)l * EE, gh);
        // ff = gelu(h @ wfc + bfc)   [2048, 4096]
        k_gemm_nn<true, false><<<dim3(FF_ / 128, M / 128), 256>>>(
            gh, wfc + (size_t)l * EE * FF_, bfc + (size_t)l * FF_,
            gff, M, FF_, EE);
        // x += ff @ wout + bout
        k_gemm_nn<false, true><<<dim3(EE / 128, M / 128), 256>>>(
            gff, wout + (size_t)l * FF_ * EE, bout + (size_t)l * EE,
            gx, M, EE, FF_);
    }

    // final ln + tied head
    k_ln<<<M, 256>>>(gx, lnf_g, lnf_b, gh);
    k_gemm_nt<<<dim3((VV + 127) / 128, M / 128), 256>>>(
        gh, wte, logits, M, VV, EE);
}

// round 13
// speedup vs baseline: 1.1561x; 1.1561x over previous
#include <cuda_runtime.h>
#include <math.h>
#include <stdint.h>
#include <mma.h>

using namespace nvcuda;

// Problem constants
#define BB   2
#define TT   1024
#define LL   6
#define HH   16
#define EE   1024
#define FF_  4096
#define HD_  64
#define VV   50257
#define EPSF 1e-5f

// ---------------- scratch (device globals; no allocations allowed) ----------
__device__ float g_x  [BB*TT*EE];     // residual stream
__device__ float g_h  [BB*TT*EE];     // layernorm output
__device__ float g_qkv[BB*TT*3*EE];   // qkv projections
__device__ float g_y  [BB*TT*EE];     // attention output
__device__ float g_ff [BB*TT*FF_];    // MLP hidden

// ---------------- embedding: x = wte[idx] + wpe[t] ---------------------------
__global__ void k_embed(const int* __restrict__ idx,
                        const float* __restrict__ wte,
                        const float* __restrict__ wpe) {
    int row = blockIdx.x;          // b*TT + t
    int t   = row % TT;
    int tok = idx[row];
    const float* wt = wte + (size_t)tok * EE;
    const float* wp = wpe + (size_t)t   * EE;
    float* xr = g_x + (size_t)row * EE;
    for (int e = threadIdx.x; e < EE; e += blockDim.x)
        xr[e] = wt[e] + wp[e];
}

// ---------------- layernorm (one block of 256 per row, warp-shuffle reduce) --
__global__ void __launch_bounds__(256)
k_ln(const float* __restrict__ x,
     const float* __restrict__ g,
     const float* __restrict__ b,
     float* __restrict__ out) {
    int row = blockIdx.x;
    const float* xr = x + (size_t)row * EE;
    int tid = threadIdx.x;

    float4 v = ((const float4*)xr)[tid];
    float s  = v.x + v.y + v.z + v.w;
    float s2 = v.x*v.x + v.y*v.y + v.z*v.z + v.w*v.w;

    #pragma unroll
    for (int o = 16; o > 0; o >>= 1) {
        s  += __shfl_xor_sync(0xffffffffu, s,  o);
        s2 += __shfl_xor_sync(0xffffffffu, s2, o);
    }
    __shared__ float ws[8], wq[8];
    int warp = tid >> 5, lane = tid & 31;
    if (lane == 0) { ws[warp] = s; wq[warp] = s2; }
    __syncthreads();
    if (warp == 0) {
        float a = (lane < 8) ? ws[lane] : 0.f;
        float c = (lane < 8) ? wq[lane] : 0.f;
        #pragma unroll
        for (int o = 4; o > 0; o >>= 1) {
            a += __shfl_xor_sync(0xffffffffu, a, o);
            c += __shfl_xor_sync(0xffffffffu, c, o);
        }
        if (lane == 0) { ws[0] = a; wq[0] = c; }
    }
    __syncthreads();
    float m   = ws[0] * (1.0f / EE);
    float var = wq[0] * (1.0f / EE) - m * m;
    float inv = rsqrtf(var + EPSF);

    float4 gv = ((const float4*)g)[tid];
    float4 bv = ((const float4*)b)[tid];
    float4 o4;
    o4.x = (v.x - m) * inv * gv.x + bv.x;
    o4.y = (v.y - m) * inv * gv.y + bv.y;
    o4.z = (v.z - m) * inv * gv.z + bv.z;
    o4.w = (v.w - m) * inv * gv.w + bv.w;
    ((float4*)(out + (size_t)row * EE))[tid] = o4;
}

__device__ __forceinline__ float gelu_exact(float v) {
    return 0.5f * v * (1.0f + erff(v * 0.70710678118654752f));
}

// ---------------- WMMA tf32 GEMM NN: C = act(A@B + bias (+resid)) ------------
// 128x128 block tile, K-tile 16, 256 threads = 8 warps (2x4), warp tile 64x32.
// Double-buffered smem, global->reg prefetch, 1 sync per K-tile.
// As[.][m][k] ldm 20 (fragment bases: m0 mult of 16 -> m0*80B mult of 32 ✓).
// Bs[.][k][n] ldm 136 (n0 mult of 16 -> 64B-aligned bases ✓).
// M,N multiples of 128; K multiple of 16.
template<bool GELU, bool RESID>
__global__ void __launch_bounds__(256)
k_wgemm_nn(const float* __restrict__ A, const float* __restrict__ Bw,
           const float* __restrict__ bias, float* __restrict__ C,
           int M, int N, int K) {
    __shared__ float As[2][128][20];
    __shared__ float Bs[2][16][136];
    int tid = threadIdx.x;
    int wid = tid >> 5, lane = tid & 31;
    int wr = wid >> 2, wc = wid & 3;            // warp row 0..1, col 0..3
    int rb = blockIdx.y * 128, cb = blockIdx.x * 128;

    int arow = tid >> 1, ak = (tid & 1) * 8;    // A: 128 rows x 16 k
    int bkr  = tid >> 5, bc = (tid & 31) * 4;   // B: 16 k x 128 n

    const float* Aptr = A  + (size_t)(rb + arow) * K;
    const float* Bp0  = Bw + (size_t)bkr * N + cb + bc;

    float4 a0 = *(const float4*)(Aptr + ak);
    float4 a1 = *(const float4*)(Aptr + ak + 4);
    float4 b0 = *(const float4*)(Bp0);
    float4 b1 = *(const float4*)(Bp0 + (size_t)8 * N);

    *(float4*)&As[0][arow][ak]     = a0;
    *(float4*)&As[0][arow][ak + 4] = a1;
    *(float4*)&Bs[0][bkr    ][bc]  = b0;
    *(float4*)&Bs[0][bkr + 8][bc]  = b1;
    __syncthreads();

    wmma::fragment<wmma::accumulator, 16, 16, 8, float> fc[4][2];
    #pragma unroll
    for (int i = 0; i < 4; i++)
        #pragma unroll
        for (int j = 0; j < 2; j++) wmma::fill_fragment(fc[i][j], 0.f);

    int nk = K >> 4, p = 0;
    for (int kt = 0; kt < nk; kt++) {
        if (kt + 1 < nk) {
            int k0 = (kt + 1) << 4;
            a0 = *(const float4*)(Aptr + k0 + ak);
            a1 = *(const float4*)(Aptr + k0 + ak + 4);
            b0 = *(const float4*)(Bp0 + (size_t)k0 * N);
            b1 = *(const float4*)(Bp0 + (size_t)(k0 + 8) * N);
        }
        #pragma unroll
        for (int ks = 0; ks < 16; ks += 8) {
            wmma::fragment<wmma::matrix_a, 16, 16, 8, wmma::precision::tf32, wmma::row_major> fa[4];
            wmma::fragment<wmma::matrix_b, 16, 16, 8, wmma::precision::tf32, wmma::row_major> fb[2];
            #pragma unroll
            for (int i = 0; i < 4; i++) {
                wmma::load_matrix_sync(fa[i], &As[p][wr * 64 + i * 16][ks], 20);
                #pragma unroll
                for (int t = 0; t < fa[i].num_elements; t++)
                    fa[i].x[t] = wmma::__float_to_tf32(fa[i].x[t]);
            }
            #pragma unroll
            for (int j = 0; j < 2; j++) {
                wmma::load_matrix_sync(fb[j], &Bs[p][ks][wc * 32 + j * 16], 136);
                #pragma unroll
                for (int t = 0; t < fb[j].num_elements; t++)
                    fb[j].x[t] = wmma::__float_to_tf32(fb[j].x[t]);
            }
            #pragma unroll
            for (int i = 0; i < 4; i++)
                #pragma unroll
                for (int j = 0; j < 2; j++)
                    wmma::mma_sync(fc[i][j], fa[i], fb[j], fc[i][j]);
        }
        if (kt + 1 < nk) {
            int q = p ^ 1;
            *(float4*)&As[q][arow][ak]     = a0;
            *(float4*)&As[q][arow][ak + 4] = a1;
            *(float4*)&Bs[q][bkr    ][bc]  = b0;
            *(float4*)&Bs[q][bkr + 8][bc]  = b1;
        }
        __syncthreads();
        p ^= 1;
    }

    // Epilogue: stage each 16x16 accum tile through smem (disjoint per warp).
    float* stg = &As[0][0][0] + wid * 256;      // 1KB-aligned per warp
    int r = lane >> 1, c8 = (lane & 1) * 8;     // each lane: 1 row, 8 cols
    #pragma unroll
    for (int i = 0; i < 4; i++) {
        #pragma unroll
        for (int j = 0; j < 2; j++) {
            wmma::store_matrix_sync(stg, fc[i][j], 16, wmma::mem_row_major);
            __syncwarp();
            int m0 = rb + wr * 64 + i * 16;
            int n0 = cb + wc * 32 + j * 16;
            float* crow = C + (size_t)(m0 + r) * N + n0 + c8;
            const float* brow = bias + n0 + c8;
            #pragma unroll
            for (int e = 0; e < 8; e++) {
                float v = stg[r * 16 + c8 + e] + brow[e];
                if (RESID) v += crow[e];
                if (GELU)  v = gelu_exact(v);
                crow[e] = v;
            }
            __syncwarp();
        }
    }
}

// ---------------- WMMA tf32 GEMM NT (head): C[M,N] = A[M,K] @ B[N,K]^T -------
// B rows are n-rows (K-contiguous) -> matrix_b col_major from Bs[n][k].
// N edge-guarded (V=50257, ODD: scalar guarded epilogue stores only).
__global__ void __launch_bounds__(256)
k_wgemm_nt(const float* __restrict__ A, const float* __restrict__ Bw,
           float* __restrict__ C, int M, int N, int K) {
    __shared__ float As[2][128][20];
    __shared__ float Bs[2][128][20];
    int tid = threadIdx.x;
    int wid = tid >> 5, lane = tid & 31;
    int wr = wid >> 2, wc = wid & 3;
    int rb = blockIdx.y * 128, cb = blockIdx.x * 128;

    int row = tid >> 1, kq = (tid & 1) * 8;     // 128 rows x 16 k, both tiles

    const float* Aptr = A + (size_t)(rb + row) * K;
    int nidx = cb + row;
    bool nvalid = nidx < N;
    const float* Bptr = Bw + (size_t)(nvalid ? nidx : 0) * K;

    float4 a0 = *(const float4*)(Aptr + kq);
    float4 a1 = *(const float4*)(Aptr + kq + 4);
    float4 b0 = make_float4(0.f, 0.f, 0.f, 0.f), b1 = b0;
    if (nvalid) { b0 = *(const float4*)(Bptr + kq); b1 = *(const float4*)(Bptr + kq + 4); }

    *(float4*)&As[0][row][kq]     = a0;
    *(float4*)&As[0][row][kq + 4] = a1;
    *(float4*)&Bs[0][row][kq]     = b0;
    *(float4*)&Bs[0][row][kq + 4] = b1;
    __syncthreads();

    wmma::fragment<wmma::accumulator, 16, 16, 8, float> fc[4][2];
    #pragma unroll
    for (int i = 0; i < 4; i++)
        #pragma unroll
        for (int j = 0; j < 2; j++) wmma::fill_fragment(fc[i][j], 0.f);

    int nk = K >> 4, p = 0;
    for (int kt = 0; kt < nk; kt++) {
        if (kt + 1 < nk) {
            int k0 = (kt + 1) << 4;
            a0 = *(const float4*)(Aptr + k0 + kq);
            a1 = *(const float4*)(Aptr + k0 + kq + 4);
            if (nvalid) {
                b0 = *(const float4*)(Bptr + k0 + kq);
                b1 = *(const float4*)(Bptr + k0 + kq + 4);
            }
        }
        #pragma unroll
        for (int ks = 0; ks < 16; ks += 8) {
            wmma::fragment<wmma::matrix_a, 16, 16, 8, wmma::precision::tf32, wmma::row_major> fa[4];
            wmma::fragment<wmma::matrix_b, 16, 16, 8, wmma::precision::tf32, wmma::col_major> fb[2];
            #pragma unroll
            for (int i = 0; i < 4; i++) {
                wmma::load_matrix_sync(fa[i], &As[p][wr * 64 + i * 16][ks], 20);
                #pragma unroll
                for (int t = 0; t < fa[i].num_elements; t++)
                    fa[i].x[t] = wmma::__float_to_tf32(fa[i].x[t]);
            }
            #pragma unroll
            for (int j = 0; j < 2; j++) {
                wmma::load_matrix_sync(fb[j], &Bs[p][wc * 32 + j * 16][ks], 20);
                #pragma unroll
                for (int t = 0; t < fb[j].num_elements; t++)
                    fb[j].x[t] = wmma::__float_to_tf32(fb[j].x[t]);
            }
            #pragma unroll
            for (int i = 0; i < 4; i++)
                #pragma unroll
                for (int j = 0; j < 2; j++)
                    wmma::mma_sync(fc[i][j], fa[i], fb[j], fc[i][j]);
        }
        if (kt + 1 < nk) {
            int q = p ^ 1;
            *(float4*)&As[q][row][kq]     = a0;
            *(float4*)&As[q][row][kq + 4] = a1;
            *(float4*)&Bs[q][row][kq]     = b0;
            *(float4*)&Bs[q][row][kq + 4] = b1;
        }
        __syncthreads();
        p ^= 1;
    }

    // Scalar guarded epilogue (N odd: rows not 16B-aligned; R10 lesson).
    float* stg = &As[0][0][0] + wid * 256;
    int r = lane >> 1, c8 = (lane & 1) * 8;
    #pragma unroll
    for (int i = 0; i < 4; i++) {
        #pragma unroll
        for (int j = 0; j < 2; j++) {
            wmma::store_matrix_sync(stg, fc[i][j], 16, wmma::mem_row_major);
            __syncwarp();
            int m0 = rb + wr * 64 + i * 16;
            int n0 = cb + wc * 32 + j * 16;
            float* crow = C + (size_t)(m0 + r) * N;
            #pragma unroll
            for (int e = 0; e < 8; e++) {
                int c = n0 + c8 + e;
                if (c < N) crow[c] = stg[r * 16 + c8 + e];
            }
            __syncwarp();
        }
    }
}

// ---------------- attention: one block per (b, h, q-row), flash-lite --------
__global__ void __launch_bounds__(128)
k_attn(const float* __restrict__ qkv, float* __restrict__ y) {
    int qi = blockIdx.x, h = blockIdx.y, b = blockIdx.z;
    __shared__ float qs[HD_];
    __shared__ float s[TT];
    __shared__ float red[128];
    int tid = threadIdx.x;
    const float scale = 0.125f;   // 1/sqrt(64)

    if (tid < HD_)
        qs[tid] = qkv[((size_t)(b * TT + qi)) * (3 * EE) + h * HD_ + tid] * scale;
    __syncthreads();

    float lmax = -1e30f;
    for (int j = tid; j <= qi; j += 128) {
        const float4* kr = (const float4*)(qkv + ((size_t)(b * TT + j)) * (3 * EE)
                                           + EE + h * HD_);
        float d = 0.f;
        #pragma unroll
        for (int e = 0; e < HD_ / 4; e++) {
            float4 kv = kr[e];
            d += qs[4*e+0]*kv.x + qs[4*e+1]*kv.y + qs[4*e+2]*kv.z + qs[4*e+3]*kv.w;
        }
        s[j] = d;
        lmax = fmaxf(lmax, d);
    }
    red[tid] = lmax;
    __syncthreads();
    for (int o = 64; o > 0; o >>= 1) {
        if (tid < o) red[tid] = fmaxf(red[tid], red[tid + o]);
        __syncthreads();
    }
    float mx = red[0];
    __syncthreads();

    float lsum = 0.f;
    for (int j = tid; j <= qi; j += 128) {
        float p = expf(s[j] - mx);
        s[j] = p;
        lsum += p;
    }
    red[tid] = lsum;
    __syncthreads();
    for (int o = 64; o > 0; o >>= 1) {
        if (tid < o) red[tid] += red[tid + o];
        __syncthreads();
    }
    float inv = 1.0f / red[0];
    __syncthreads();

    int d    = tid & 63;
    int half = tid >> 6;
    float acc = 0.f;
    for (int j = half; j <= qi; j += 2) {
        const float* vr = qkv + ((size_t)(b * TT + j)) * (3 * EE) + 2 * EE + h * HD_;
        acc += s[j] * vr[d];
    }
    red[tid] = acc;
    __syncthreads();
    if (half == 0) {
        float r = (red[tid] + red[tid + 64]) * inv;
        y[((size_t)(b * TT + qi)) * EE + h * HD_ + d] = r;
    }
}

// ---------------- driver ------------------------------------------------------
extern "C" void kernel_launch(void* const* d_in, const int* in_sizes, int n_in,
                              void* d_out, int out_size) {
    const int*   idx   = (const int*)  d_in[0];
    const float* wte   = (const float*)d_in[1];
    const float* wpe   = (const float*)d_in[2];
    const float* ln1_g = (const float*)d_in[3];
    const float* ln1_b = (const float*)d_in[4];
    const float* wqkv  = (const float*)d_in[5];
    const float* bqkv  = (const float*)d_in[6];
    const float* wproj = (const float*)d_in[7];
    const float* bproj = (const float*)d_in[8];
    const float* ln2_g = (const float*)d_in[9];
    const float* ln2_b = (const float*)d_in[10];
    const float* wfc   = (const float*)d_in[11];
    const float* bfc   = (const float*)d_in[12];
    const float* wout  = (const float*)d_in[13];
    const float* bout  = (const float*)d_in[14];
    const float* lnf_g = (const float*)d_in[15];
    const float* lnf_b = (const float*)d_in[16];
    float* logits = (float*)d_out;

    float *gx, *gh, *gqkv, *gy, *gff;
    cudaGetSymbolAddress((void**)&gx,   g_x);
    cudaGetSymbolAddress((void**)&gh,   g_h);
    cudaGetSymbolAddress((void**)&gqkv, g_qkv);
    cudaGetSymbolAddress((void**)&gy,   g_y);
    cudaGetSymbolAddress((void**)&gff,  g_ff);

    const int M = BB * TT;  // 2048

    k_embed<<<M, 256>>>(idx, wte, wpe);

    for (int l = 0; l < LL; l++) {
        // ln1
        k_ln<<<M, 256>>>(gx, ln1_g + (size_t)l * EE, ln1_b + (size_t)l * EE, gh);
        // qkv = h @ wqkv + bqkv   [2048, 3072]
        k_wgemm_nn<false, false><<<dim3(3 * EE / 128, M / 128), 256>>>(
            gh, wqkv + (size_t)l * EE * 3 * EE, bqkv + (size_t)l * 3 * EE,
            gqkv, M, 3 * EE, EE);
        // attention
        k_attn<<<dim3(TT, HH, BB), 128>>>(gqkv, gy);
        // x += y @ wproj + bproj
        k_wgemm_nn<false, true><<<dim3(EE / 128, M / 128), 256>>>(
            gy, wproj + (size_t)l * EE * EE, bproj + (size_t)l * EE,
            gx, M, EE, EE);
        // ln2
        k_ln<<<M, 256>>>(gx, ln2_g + (size_t)l * EE, ln2_b + (size_t)l * EE, gh);
        // ff = gelu(h @ wfc + bfc)   [2048, 4096]
        k_wgemm_nn<true, false><<<dim3(FF_ / 128, M / 128), 256>>>(
            gh, wfc + (size_t)l * EE * FF_, bfc + (size_t)l * FF_,
            gff, M, FF_, EE);
        // x += ff @ wout + bout
        k_wgemm_nn<false, true><<<dim3(EE / 128, M / 128), 256>>>(
            gff, wout + (size_t)l * FF_ * EE, bout + (size_t)l * EE,
            gx, M, EE, FF_);
    }

    // final ln + tied head
    k_ln<<<M, 256>>>(gx, lnf_g, lnf_b, gh);
    k_wgemm_nt<<<dim3((VV + 127) / 128, M / 128), 256>>>(
        gh, wte, logits, M, VV, EE);
}

// round 17
// speedup vs baseline: 1.1608x; 1.0041x over previous
#include <cuda_runtime.h>
#include <math.h>
#include <stdint.h>
#include <mma.h>

using namespace nvcuda;

// Problem constants
#define BB   2
#define TT   1024
#define LL   6
#define HH   16
#define EE   1024
#define FF_  4096
#define HD_  64
#define VV   50257
#define EPSF 1e-5f

// ---------------- scratch (device globals; no allocations allowed) ----------
__device__ float g_x  [BB*TT*EE];     // residual stream
__device__ float g_h  [BB*TT*EE];     // layernorm output
__device__ float g_qkv[BB*TT*3*EE];   // qkv projections
__device__ float g_y  [BB*TT*EE];     // attention output
__device__ float g_ff [BB*TT*FF_];    // MLP hidden

// ---------------- embedding: x = wte[idx] + wpe[t] ---------------------------
__global__ void k_embed(const int* __restrict__ idx,
                        const float* __restrict__ wte,
                        const float* __restrict__ wpe) {
    int row = blockIdx.x;          // b*TT + t
    int t   = row % TT;
    int tok = idx[row];
    const float* wt = wte + (size_t)tok * EE;
    const float* wp = wpe + (size_t)t   * EE;
    float* xr = g_x + (size_t)row * EE;
    for (int e = threadIdx.x; e < EE; e += blockDim.x)
        xr[e] = wt[e] + wp[e];
}

// ---------------- layernorm (one block of 256 per row, warp-shuffle reduce) --
__global__ void __launch_bounds__(256)
k_ln(const float* __restrict__ x,
     const float* __restrict__ g,
     const float* __restrict__ b,
     float* __restrict__ out) {
    int row = blockIdx.x;
    const float* xr = x + (size_t)row * EE;
    int tid = threadIdx.x;

    float4 v = ((const float4*)xr)[tid];
    float s  = v.x + v.y + v.z + v.w;
    float s2 = v.x*v.x + v.y*v.y + v.z*v.z + v.w*v.w;

    #pragma unroll
    for (int o = 16; o > 0; o >>= 1) {
        s  += __shfl_xor_sync(0xffffffffu, s,  o);
        s2 += __shfl_xor_sync(0xffffffffu, s2, o);
    }
    __shared__ float ws[8], wq[8];
    int warp = tid >> 5, lane = tid & 31;
    if (lane == 0) { ws[warp] = s; wq[warp] = s2; }
    __syncthreads();
    if (warp == 0) {
        float a = (lane < 8) ? ws[lane] : 0.f;
        float c = (lane < 8) ? wq[lane] : 0.f;
        #pragma unroll
        for (int o = 4; o > 0; o >>= 1) {
            a += __shfl_xor_sync(0xffffffffu, a, o);
            c += __shfl_xor_sync(0xffffffffu, c, o);
        }
        if (lane == 0) { ws[0] = a; wq[0] = c; }
    }
    __syncthreads();
    float m   = ws[0] * (1.0f / EE);
    float var = wq[0] * (1.0f / EE) - m * m;
    float inv = rsqrtf(var + EPSF);

    float4 gv = ((const float4*)g)[tid];
    float4 bv = ((const float4*)b)[tid];
    float4 o4;
    o4.x = (v.x - m) * inv * gv.x + bv.x;
    o4.y = (v.y - m) * inv * gv.y + bv.y;
    o4.z = (v.z - m) * inv * gv.z + bv.z;
    o4.w = (v.w - m) * inv * gv.w + bv.w;
    ((float4*)(out + (size_t)row * EE))[tid] = o4;
}

__device__ __forceinline__ float gelu_exact(float v) {
    return 0.5f * v * (1.0f + erff(v * 0.70710678118654752f));
}

// tf32-truncate a float4 once, at smem store time (idempotent with the
// per-fragment conversion the WMMA API would otherwise do).
__device__ __forceinline__ float4 to_tf32_4(float4 v) {
    v.x = wmma::__float_to_tf32(v.x);
    v.y = wmma::__float_to_tf32(v.y);
    v.z = wmma::__float_to_tf32(v.z);
    v.w = wmma::__float_to_tf32(v.w);
    return v;
}

// ---------------- WMMA tf32 GEMM NN: C = act(A@B + bias (+resid)) ------------
// 128x128 block tile, K-tile 16, 256 threads = 8 warps (2x4), warp tile 64x32.
// Double-buffered smem, global->reg prefetch, 1 sync per K-tile.
// tf32 conversion done ONCE at smem store; fragments used directly (R16 opt).
// As[.][m][k] ldm 20; Bs[.][k][n] ldm 132 (132%32=4 -> conflict-free k-rows).
// M,N multiples of 128; K multiple of 16.
template<bool GELU, bool RESID>
__global__ void __launch_bounds__(256)
k_wgemm_nn(const float* __restrict__ A, const float* __restrict__ Bw,
           const float* __restrict__ bias, float* __restrict__ C,
           int M, int N, int K) {
    __shared__ float As[2][128][20];
    __shared__ float Bs[2][16][132];
    int tid = threadIdx.x;
    int wid = tid >> 5, lane = tid & 31;
    int wr = wid >> 2, wc = wid & 3;            // warp row 0..1, col 0..3
    int rb = blockIdx.y * 128, cb = blockIdx.x * 128;

    int arow = tid >> 1, ak = (tid & 1) * 8;    // A: 128 rows x 16 k
    int bkr  = tid >> 5, bc = (tid & 31) * 4;   // B: 16 k x 128 n

    const float* Aptr = A  + (size_t)(rb + arow) * K;
    const float* Bp0  = Bw + (size_t)bkr * N + cb + bc;

    float4 a0 = *(const float4*)(Aptr + ak);
    float4 a1 = *(const float4*)(Aptr + ak + 4);
    float4 b0 = *(const float4*)(Bp0);
    float4 b1 = *(const float4*)(Bp0 + (size_t)8 * N);

    *(float4*)&As[0][arow][ak]     = to_tf32_4(a0);
    *(float4*)&As[0][arow][ak + 4] = to_tf32_4(a1);
    *(float4*)&Bs[0][bkr    ][bc]  = to_tf32_4(b0);
    *(float4*)&Bs[0][bkr + 8][bc]  = to_tf32_4(b1);
    __syncthreads();

    wmma::fragment<wmma::accumulator, 16, 16, 8, float> fc[4][2];
    #pragma unroll
    for (int i = 0; i < 4; i++)
        #pragma unroll
        for (int j = 0; j < 2; j++) wmma::fill_fragment(fc[i][j], 0.f);

    int nk = K >> 4, p = 0;
    for (int kt = 0; kt < nk; kt++) {
        if (kt + 1 < nk) {
            int k0 = (kt + 1) << 4;
            a0 = *(const float4*)(Aptr + k0 + ak);
            a1 = *(const float4*)(Aptr + k0 + ak + 4);
            b0 = *(const float4*)(Bp0 + (size_t)k0 * N);
            b1 = *(const float4*)(Bp0 + (size_t)(k0 + 8) * N);
        }
        #pragma unroll
        for (int ks = 0; ks < 16; ks += 8) {
            wmma::fragment<wmma::matrix_a, 16, 16, 8, wmma::precision::tf32, wmma::row_major> fa[4];
            wmma::fragment<wmma::matrix_b, 16, 16, 8, wmma::precision::tf32, wmma::row_major> fb[2];
            #pragma unroll
            for (int i = 0; i < 4; i++)
                wmma::load_matrix_sync(fa[i], &As[p][wr * 64 + i * 16][ks], 20);
            #pragma unroll
            for (int j = 0; j < 2; j++)
                wmma::load_matrix_sync(fb[j], &Bs[p][ks][wc * 32 + j * 16], 132);
            #pragma unroll
            for (int i = 0; i < 4; i++)
                #pragma unroll
                for (int j = 0; j < 2; j++)
                    wmma::mma_sync(fc[i][j], fa[i], fb[j], fc[i][j]);
        }
        if (kt + 1 < nk) {
            int q = p ^ 1;
            *(float4*)&As[q][arow][ak]     = to_tf32_4(a0);
            *(float4*)&As[q][arow][ak + 4] = to_tf32_4(a1);
            *(float4*)&Bs[q][bkr    ][bc]  = to_tf32_4(b0);
            *(float4*)&Bs[q][bkr + 8][bc]  = to_tf32_4(b1);
        }
        __syncthreads();
        p ^= 1;
    }

    // Epilogue: stage each 16x16 accum tile through smem (disjoint per warp).
    float* stg = &As[0][0][0] + wid * 256;      // 1KB-aligned per warp
    int r = lane >> 1, c8 = (lane & 1) * 8;     // each lane: 1 row, 8 cols
    #pragma unroll
    for (int i = 0; i < 4; i++) {
        #pragma unroll
        for (int j = 0; j < 2; j++) {
            wmma::store_matrix_sync(stg, fc[i][j], 16, wmma::mem_row_major);
            __syncwarp();
            int m0 = rb + wr * 64 + i * 16;
            int n0 = cb + wc * 32 + j * 16;
            float* crow = C + (size_t)(m0 + r) * N + n0 + c8;
            const float* brow = bias + n0 + c8;
            #pragma unroll
            for (int e = 0; e < 8; e++) {
                float v = stg[r * 16 + c8 + e] + brow[e];
                if (RESID) v += crow[e];
                if (GELU)  v = gelu_exact(v);
                crow[e] = v;
            }
            __syncwarp();
        }
    }
}

// ---------------- WMMA tf32 GEMM NT (head): C[M,N] = A[M,K] @ B[N,K]^T -------
// B rows are n-rows (K-contiguous) -> matrix_b col_major from Bs[n][k].
// N edge-guarded (V=50257, ODD: scalar guarded epilogue stores only).
__global__ void __launch_bounds__(256)
k_wgemm_nt(const float* __restrict__ A, const float* __restrict__ Bw,
           float* __restrict__ C, int M, int N, int K) {
    __shared__ float As[2][128][20];
    __shared__ float Bs[2][128][20];
    int tid = threadIdx.x;
    int wid = tid >> 5, lane = tid & 31;
    int wr = wid >> 2, wc = wid & 3;
    int rb = blockIdx.y * 128, cb = blockIdx.x * 128;

    int row = tid >> 1, kq = (tid & 1) * 8;     // 128 rows x 16 k, both tiles

    const float* Aptr = A + (size_t)(rb + row) * K;
    int nidx = cb + row;
    bool nvalid = nidx < N;
    const float* Bptr = Bw + (size_t)(nvalid ? nidx : 0) * K;

    float4 a0 = *(const float4*)(Aptr + kq);
    float4 a1 = *(const float4*)(Aptr + kq + 4);
    float4 b0 = make_float4(0.f, 0.f, 0.f, 0.f), b1 = b0;
    if (nvalid) { b0 = *(const float4*)(Bptr + kq); b1 = *(const float4*)(Bptr + kq + 4); }

    *(float4*)&As[0][row][kq]     = to_tf32_4(a0);
    *(float4*)&As[0][row][kq + 4] = to_tf32_4(a1);
    *(float4*)&Bs[0][row][kq]     = to_tf32_4(b0);
    *(float4*)&Bs[0][row][kq + 4] = to_tf32_4(b1);
    __syncthreads();

    wmma::fragment<wmma::accumulator, 16, 16, 8, float> fc[4][2];
    #pragma unroll
    for (int i = 0; i < 4; i++)
        #pragma unroll
        for (int j = 0; j < 2; j++) wmma::fill_fragment(fc[i][j], 0.f);

    int nk = K >> 4, p = 0;
    for (int kt = 0; kt < nk; kt++) {
        if (kt + 1 < nk) {
            int k0 = (kt + 1) << 4;
            a0 = *(const float4*)(Aptr + k0 + kq);
            a1 = *(const float4*)(Aptr + k0 + kq + 4);
            if (nvalid) {
                b0 = *(const float4*)(Bptr + k0 + kq);
                b1 = *(const float4*)(Bptr + k0 + kq + 4);
            }
        }
        #pragma unroll
        for (int ks = 0; ks < 16; ks += 8) {
            wmma::fragment<wmma::matrix_a, 16, 16, 8, wmma::precision::tf32, wmma::row_major> fa[4];
            wmma::fragment<wmma::matrix_b, 16, 16, 8, wmma::precision::tf32, wmma::col_major> fb[2];
            #pragma unroll
            for (int i = 0; i < 4; i++)
                wmma::load_matrix_sync(fa[i], &As[p][wr * 64 + i * 16][ks], 20);
            #pragma unroll
            for (int j = 0; j < 2; j++)
                wmma::load_matrix_sync(fb[j], &Bs[p][wc * 32 + j * 16][ks], 20);
            #pragma unroll
            for (int i = 0; i < 4; i++)
                #pragma unroll
                for (int j = 0; j < 2; j++)
                    wmma::mma_sync(fc[i][j], fa[i], fb[j], fc[i][j]);
        }
        if (kt + 1 < nk) {
            int q = p ^ 1;
            *(float4*)&As[q][row][kq]     = to_tf32_4(a0);
            *(float4*)&As[q][row][kq + 4] = to_tf32_4(a1);
            *(float4*)&Bs[q][row][kq]     = to_tf32_4(b0);
            *(float4*)&Bs[q][row][kq + 4] = to_tf32_4(b1);
        }
        __syncthreads();
        p ^= 1;
    }

    // Scalar guarded epilogue (N odd: rows not 16B-aligned; R10 lesson).
    float* stg = &As[0][0][0] + wid * 256;
    int r = lane >> 1, c8 = (lane & 1) * 8;
    #pragma unroll
    for (int i = 0; i < 4; i++) {
        #pragma unroll
        for (int j = 0; j < 2; j++) {
            wmma::store_matrix_sync(stg, fc[i][j], 16, wmma::mem_row_major);
            __syncwarp();
            int m0 = rb + wr * 64 + i * 16;
            int n0 = cb + wc * 32 + j * 16;
            float* crow = C + (size_t)(m0 + r) * N;
            #pragma unroll
            for (int e = 0; e < 8; e++) {
                int c = n0 + c8 + e;
                if (c < N) crow[c] = stg[r * 16 + c8 + e];
            }
            __syncwarp();
        }
    }
}

// ---------------- attention: one block per (b, h, q-row), flash-lite --------
__global__ void __launch_bounds__(128)
k_attn(const float* __restrict__ qkv, float* __restrict__ y) {
    int qi = blockIdx.x, h = blockIdx.y, b = blockIdx.z;
    __shared__ float qs[HD_];
    __shared__ float s[TT];
    __shared__ float red[128];
    int tid = threadIdx.x;
    const float scale = 0.125f;   // 1/sqrt(64)

    if (tid < HD_)
        qs[tid] = qkv[((size_t)(b * TT + qi)) * (3 * EE) + h * HD_ + tid] * scale;
    __syncthreads();

    float lmax = -1e30f;
    for (int j = tid; j <= qi; j += 128) {
        const float4* kr = (const float4*)(qkv + ((size_t)(b * TT + j)) * (3 * EE)
                                           + EE + h * HD_);
        float d = 0.f;
        #pragma unroll
        for (int e = 0; e < HD_ / 4; e++) {
            float4 kv = kr[e];
            d += qs[4*e+0]*kv.x + qs[4*e+1]*kv.y + qs[4*e+2]*kv.z + qs[4*e+3]*kv.w;
        }
        s[j] = d;
        lmax = fmaxf(lmax, d);
    }
    red[tid] = lmax;
    __syncthreads();
    for (int o = 64; o > 0; o >>= 1) {
        if (tid < o) red[tid] = fmaxf(red[tid], red[tid + o]);
        __syncthreads();
    }
    float mx = red[0];
    __syncthreads();

    float lsum = 0.f;
    for (int j = tid; j <= qi; j += 128) {
        float p = expf(s[j] - mx);
        s[j] = p;
        lsum += p;
    }
    red[tid] = lsum;
    __syncthreads();
    for (int o = 64; o > 0; o >>= 1) {
        if (tid < o) red[tid] += red[tid + o];
        __syncthreads();
    }
    float inv = 1.0f / red[0];
    __syncthreads();

    int d    = tid & 63;
    int half = tid >> 6;
    float acc = 0.f;
    for (int j = half; j <= qi; j += 2) {
        const float* vr = qkv + ((size_t)(b * TT + j)) * (3 * EE) + 2 * EE + h * HD_;
        acc += s[j] * vr[d];
    }
    red[tid] = acc;
    __syncthreads();
    if (half == 0) {
        float r = (red[tid] + red[tid + 64]) * inv;
        y[((size_t)(b * TT + qi)) * EE + h * HD_ + d] = r;
    }
}

// ---------------- driver ------------------------------------------------------
extern "C" void kernel_launch(void* const* d_in, const int* in_sizes, int n_in,
                              void* d_out, int out_size) {
    const int*   idx   = (const int*)  d_in[0];
    const float* wte   = (const float*)d_in[1];
    const float* wpe   = (const float*)d_in[2];
    const float* ln1_g = (const float*)d_in[3];
    const float* ln1_b = (const float*)d_in[4];
    const float* wqkv  = (const float*)d_in[5];
    const float* bqkv  = (const float*)d_in[6];
    const float* wproj = (const float*)d_in[7];
    const float* bproj = (const float*)d_in[8];
    const float* ln2_g = (const float*)d_in[9];
    const float* ln2_b = (const float*)d_in[10];
    const float* wfc   = (const float*)d_in[11];
    const float* bfc   = (const float*)d_in[12];
    const float* wout  = (const float*)d_in[13];
    const float* bout  = (const float*)d_in[14];
    const float* lnf_g = (const float*)d_in[15];
    const float* lnf_b = (const float*)d_in[16];
    float* logits = (float*)d_out;

    float *gx, *gh, *gqkv, *gy, *gff;
    cudaGetSymbolAddress((void**)&gx,   g_x);
    cudaGetSymbolAddress((void**)&gh,   g_h);
    cudaGetSymbolAddress((void**)&gqkv, g_qkv);
    cudaGetSymbolAddress((void**)&gy,   g_y);
    cudaGetSymbolAddress((void**)&gff,  g_ff);

    const int M = BB * TT;  // 2048

    k_embed<<<M, 256>>>(idx, wte, wpe);

    for (int l = 0; l < LL; l++) {
        // ln1
        k_ln<<<M, 256>>>(gx, ln1_g + (size_t)l * EE, ln1_b + (size_t)l * EE, gh);
        // qkv = h @ wqkv + bqkv   [2048, 3072]
        k_wgemm_nn<false, false><<<dim3(3 * EE / 128, M / 128), 256>>>(
            gh, wqkv + (size_t)l * EE * 3 * EE, bqkv + (size_t)l * 3 * EE,
            gqkv, M, 3 * EE, EE);
        // attention
        k_attn<<<dim3(TT, HH, BB), 128>>>(gqkv, gy);
        // x += y @ wproj + bproj
        k_wgemm_nn<false, true><<<dim3(EE / 128, M / 128), 256>>>(
            gy, wproj + (size_t)l * EE * EE, bproj + (size_t)l * EE,
            gx, M, EE, EE);
        // ln2
        k_ln<<<M, 256>>>(gx, ln2_g + (size_t)l * EE, ln2_b + (size_t)l * EE, gh);
        // ff = gelu(h @ wfc + bfc)   [2048, 4096]
        k_wgemm_nn<true, false><<<dim3(FF_ / 128, M / 128), 256>>>(
            gh, wfc + (size_t)l * EE * FF_, bfc + (size_t)l * FF_,
            gff, M, FF_, EE);
        // x += ff @ wout + bout
        k_wgemm_nn<false, true><<<dim3(EE / 128, M / 128), 256>>>(
            gff, wout + (size_t)l * FF_ * EE, bout + (size_t)l * EE,
            gx, M, EE, FF_);
    }

    // final ln + tied head
    k_ln<<<M, 256>>>(gx, lnf_g, lnf_b, gh);
    k_wgemm_nt<<<dim3((VV + 127) / 128, M / 128), 256>>>(
        gh, wte, logits, M, VV, EE);
}